// round 2
// baseline (speedup 1.0000x reference)
#include <cuda_runtime.h>

#define H 128
#define W 128
#define NCONV 8
#define TILE_ROWS 16
#define FROWS 18          // TILE_ROWS + 2 halo
#define PSTRIDE 132       // pair entries per row (129 used, padded)
#define NTHREADS 256

// dynamic smem layout (bytes)
#define OFF_P    0                                   // float2 P[4][18][132]   = 76032
#define OFF_X    76032                               // float  x[18][132]      = 9504
#define OFF_W    85536                               // u64    w[288]          = 2304
#define OFF_B    87840                               // u64    bias[8]         = 64
#define SMEM_BYTES 87904

typedef unsigned long long ull;

__device__ __forceinline__ ull pk2(float lo, float hi) {
    ull r; asm("mov.b64 %0, {%1, %2};" : "=l"(r) : "f"(lo), "f"(hi)); return r;
}
__device__ __forceinline__ void fma2(ull &d, ull a, ull b) {
    asm("fma.rn.f32x2 %0, %1, %2, %0;" : "+l"(d) : "l"(a), "l"(b));
}

__device__ __forceinline__ void feats(float xv, float &s, float &t, float &t2, float &t3) {
    float e  = __expf(-xv);
    float d1 = __fdividef(1.f, 1.f + e);
    s = xv * d1;                                  // silu
    float e2 = e * e;                             // e^{-2x}
    float d2 = __fdividef(2.f, 1.f + e2);
    t  = d2 - 1.f;                                // tanh
    t2 = fmaf(t + t, t, -1.f);                    // T2
    t3 = fmaf(t + t, t2, -t);                     // T3
}

__global__ void __launch_bounds__(NTHREADS, 2)
kan_conv_kernel(const float* __restrict__ x,
                const float* __restrict__ cheby,
                const float* __restrict__ bw,
                const float* __restrict__ ss,
                float* __restrict__ out)
{
    extern __shared__ char smem_raw[];
    float2* Pm   = (float2*)(smem_raw + OFF_P);   // [f][row][k] pairs (s[k-1], s[k])
    float*  xsm  = (float*) (smem_raw + OFF_X);   // [row][i], i = col+1
    ull*    wsm  = (ull*)   (smem_raw + OFF_W);   // [(tap*4+f)*8 + j], dup pairs
    ull*    biasd= (ull*)   (smem_raw + OFF_B);

    const int tid = threadIdx.x;
    const int blk = blockIdx.x;
    const int bc  = blk >> 3;                     // plane b*C + c
    const int r0  = (blk & 7) * TILE_ROWS;

    // ---- Phase A1: weights (duplicated f32x2 pairs) ----
    for (int idx = tid; idx < 9 * 4 * 8; idx += NTHREADS) {
        int j   = idx & 7;
        int fi  = idx >> 3;
        int tap = fi >> 2;
        int f   = fi & 3;
        float wv;
        if (f == 0) wv = bw[j * 9 + tap];
        else        wv = cheby[(j * 9 + tap) * 4 + f] * ss[j * 9 + tap];
        wsm[idx] = pk2(wv, wv);
    }
    if (tid < NCONV) {
        float s = 0.f;
        #pragma unroll
        for (int i = 0; i < 9; i++) s += cheby[(tid * 9 + i) * 4] * ss[tid * 9 + i];
        biasd[tid] = pk2(s, s);
    }

    // ---- Phase A2: x tile (with zero halo) -> scalar smem, coalesced ----
    const float* xp = x + (size_t)bc * (H * W);
    for (int idx = tid; idx < FROWS * 130; idx += NTHREADS) {
        int lr = idx / 130;
        int c  = idx - lr * 130 - 1;              // col in [-1, 128]
        int gr = r0 - 1 + lr;
        float v = 0.f;
        if ((unsigned)gr < H && (unsigned)c < W) v = xp[gr * W + c];
        xsm[lr * PSTRIDE + (c + 1)] = v;
    }
    __syncthreads();

    // ---- Phase B: features -> pre-paired smem (serial chunks, 1 compute/value) ----
    if (tid < 18 * 13) {
        int row = tid / 13;
        int q   = tid - row * 13;
        int k0  = q * 10;
        const float* xr = &xsm[row * PSTRIDE];
        float ps, pt, pt2, pt3;
        feats(xr[k0], ps, pt, pt2, pt3);          // s[k0-1] (xsm[i] = col i-1)
        int kend = k0 + 10; if (kend > 129) kend = 129;
        float2* P0 = &Pm[(0 * FROWS + row) * PSTRIDE];
        float2* P1 = &Pm[(1 * FROWS + row) * PSTRIDE];
        float2* P2 = &Pm[(2 * FROWS + row) * PSTRIDE];
        float2* P3 = &Pm[(3 * FROWS + row) * PSTRIDE];
        for (int k = k0; k < kend; k++) {
            float cs, ct, ct2, ct3;
            feats(xr[k + 1], cs, ct, ct2, ct3);   // s[k]
            P0[k] = make_float2(ps,  cs);
            P1[k] = make_float2(pt,  ct);
            P2[k] = make_float2(pt2, ct2);
            P3[k] = make_float2(pt3, ct3);
            ps = cs; pt = ct; pt2 = ct2; pt3 = ct3;
        }
    }
    __syncthreads();

    // ---- Compute: thread -> cols {c0,c0+1} & {c0+64,c0+65}, rows yb..yb+1, 8 j ----
    const int lx = tid & 31;
    const int ty = tid >> 5;
    const int c0 = lx * 2;
    const int yb = ty * 2;

    ull acc[8][2][2];                             // [j][r][g]
    #pragma unroll
    for (int j = 0; j < 8; j++) {
        ull b = biasd[j];
        acc[j][0][0] = b; acc[j][0][1] = b; acc[j][1][0] = b; acc[j][1][1] = b;
    }

    #pragma unroll
    for (int f = 0; f < 4; f++) {
        #pragma unroll
        for (int dy = 0; dy < 3; dy++) {
            ull pr[2][2][3];
            #pragma unroll
            for (int r = 0; r < 2; r++) {
                #pragma unroll
                for (int g = 0; g < 2; g++) {
                    const float2* p = &Pm[((f * FROWS) + (yb + dy + r)) * PSTRIDE + c0 + g * 64];
                    ulonglong2 v = *(const ulonglong2*)p;    // P[c0], P[c0+1]
                    pr[r][g][0] = v.x;
                    pr[r][g][1] = v.y;
                    pr[r][g][2] = *(const ull*)(p + 2);      // P[c0+2]
                }
            }
            #pragma unroll
            for (int dx = 0; dx < 3; dx++) {
                const ulonglong2* wp = (const ulonglong2*)&wsm[((dy * 3 + dx) * 4 + f) * 8];
                ulonglong2 w01 = wp[0], w23 = wp[1], w45 = wp[2], w67 = wp[3];
                #pragma unroll
                for (int r = 0; r < 2; r++) {
                    #pragma unroll
                    for (int g = 0; g < 2; g++) {
                        ull fv = pr[r][g][dx];
                        fma2(acc[0][r][g], fv, w01.x);
                        fma2(acc[1][r][g], fv, w01.y);
                        fma2(acc[2][r][g], fv, w23.x);
                        fma2(acc[3][r][g], fv, w23.y);
                        fma2(acc[4][r][g], fv, w45.x);
                        fma2(acc[5][r][g], fv, w45.y);
                        fma2(acc[6][r][g], fv, w67.x);
                        fma2(acc[7][r][g], fv, w67.y);
                    }
                }
            }
        }
    }

    // ---- stores: STG.64, fully coalesced per warp ----
    float* ob = out + ((size_t)(bc * NCONV) * H + (r0 + yb)) * W + c0;
    #pragma unroll
    for (int j = 0; j < 8; j++) {
        #pragma unroll
        for (int r = 0; r < 2; r++) {
            #pragma unroll
            for (int g = 0; g < 2; g++) {
                *(ull*)(ob + ((size_t)j * H + r) * W + g * 64) = acc[j][r][g];
            }
        }
    }
}

extern "C" void kernel_launch(void* const* d_in, const int* in_sizes, int n_in,
                              void* d_out, int out_size) {
    const float* x     = (const float*)d_in[0];
    const float* cheby = (const float*)d_in[1];   // (8, 9, 4)
    const float* bw    = (const float*)d_in[2];   // (8, 9)
    const float* ss    = (const float*)d_in[3];   // (8, 9)
    float* out = (float*)d_out;

    cudaFuncSetAttribute(kan_conv_kernel,
                         cudaFuncAttributeMaxDynamicSharedMemorySize, SMEM_BYTES);

    const int planes = 16 * 16;                   // B * C
    dim3 grid(planes * (H / TILE_ROWS));          // 2048 blocks
    kan_conv_kernel<<<grid, NTHREADS, SMEM_BYTES>>>(x, cheby, bw, ss, out);
}

// round 3
// speedup vs baseline: 1.1807x; 1.1807x over previous
#include <cuda_runtime.h>

#define H 128
#define W 128
#define NCONV 8
#define TILE_ROWS 8
#define FROWS 10          // TILE_ROWS + 2 halo
#define PSTRIDE 132       // entries per row (129 used, padded)
#define NTHREADS 256

// dynamic smem layout (bytes)
#define OFF_P    0                                   // float2 P[4][10][132] = 42240
#define OFF_X    42240                               // float  x[10][132]    = 5280
#define OFF_W    47520                               // u64    w[288]        = 2304
#define OFF_B    49824                               // u64    bias[8]       = 64
#define SMEM_BYTES 49888

typedef unsigned long long ull;

__device__ __forceinline__ ull pk2(float lo, float hi) {
    ull r; asm("mov.b64 %0, {%1, %2};" : "=l"(r) : "f"(lo), "f"(hi)); return r;
}
__device__ __forceinline__ void fma2(ull &d, ull a, ull b) {
    asm("fma.rn.f32x2 %0, %1, %2, %0;" : "+l"(d) : "l"(a), "l"(b));
}

__device__ __forceinline__ void feats(float xv, float &s, float &t, float &t2, float &t3) {
    float e  = __expf(-xv);
    float d1 = __fdividef(1.f, 1.f + e);
    s = xv * d1;                                  // silu
    float e2 = e * e;                             // e^{-2x}
    float d2 = __fdividef(2.f, 1.f + e2);
    t  = d2 - 1.f;                                // tanh
    t2 = fmaf(t + t, t, -1.f);                    // T2
    t3 = fmaf(t + t, t2, -t);                     // T3
}

__global__ void __launch_bounds__(NTHREADS, 3)
kan_conv_kernel(const float* __restrict__ x,
                const float* __restrict__ cheby,
                const float* __restrict__ bw,
                const float* __restrict__ ss,
                float* __restrict__ out)
{
    extern __shared__ char smem_raw[];
    float2* Pm    = (float2*)(smem_raw + OFF_P);  // [f][row][k]: (feat[k-1], feat[k])
    float*  xsm   = (float*) (smem_raw + OFF_X);  // [row][i], i = col+1
    ull*    wsm   = (ull*)   (smem_raw + OFF_W);  // [(tap*4+f)*8 + j] dup pairs
    ull*    biasd = (ull*)   (smem_raw + OFF_B);

    const int tid = threadIdx.x;
    const int blk = blockIdx.x;
    const int bc  = blk >> 4;                     // plane b*C + c (0..255)
    const int r0  = (blk & 15) * TILE_ROWS;       // tile top row

    // ---- Phase A1: weights -> smem (duplicated f32x2 pairs) ----
    for (int idx = tid; idx < 9 * 4 * 8; idx += NTHREADS) {
        int j   = idx & 7;
        int fi  = idx >> 3;
        int tap = fi >> 2;
        int f   = fi & 3;
        float wv;
        if (f == 0) wv = bw[j * 9 + tap];
        else        wv = cheby[(j * 9 + tap) * 4 + f] * ss[j * 9 + tap];
        wsm[idx] = pk2(wv, wv);
    }
    if (tid < NCONV) {
        float s = 0.f;
        #pragma unroll
        for (int i = 0; i < 9; i++) s += cheby[(tid * 9 + i) * 4] * ss[tid * 9 + i];
        biasd[tid] = pk2(s, s);
    }

    // ---- Phase A2: x tile (zero halo) -> scalar smem, coalesced ----
    const float* xp = x + (size_t)bc * (H * W);
    for (int idx = tid; idx < FROWS * 130; idx += NTHREADS) {
        int lr = idx / 130;
        int c  = idx - lr * 130 - 1;              // col in [-1, 128]
        int gr = r0 - 1 + lr;
        float v = 0.f;
        if ((unsigned)gr < H && (unsigned)c < W) v = xp[gr * W + c];
        xsm[lr * PSTRIDE + (c + 1)] = v;
    }
    __syncthreads();

    // ---- Phase B: features -> pre-paired smem (220 threads, chunk=6) ----
    if (tid < FROWS * 22) {
        int row = tid / 22;
        int q   = tid - row * 22;
        int k0  = q * 6;
        const float* xr = &xsm[row * PSTRIDE];
        float ps, pt, pt2, pt3;
        feats(xr[k0], ps, pt, pt2, pt3);          // feat(col k0-1)
        int kend = k0 + 6; if (kend > 129) kend = 129;
        float2* P0 = &Pm[(0 * FROWS + row) * PSTRIDE];
        float2* P1 = &Pm[(1 * FROWS + row) * PSTRIDE];
        float2* P2 = &Pm[(2 * FROWS + row) * PSTRIDE];
        float2* P3 = &Pm[(3 * FROWS + row) * PSTRIDE];
        for (int k = k0; k < kend; k++) {
            float cs, ct, ct2, ct3;
            feats(xr[k + 1], cs, ct, ct2, ct3);   // feat(col k)
            P0[k] = make_float2(ps,  cs);
            P1[k] = make_float2(pt,  ct);
            P2[k] = make_float2(pt2, ct2);
            P3[k] = make_float2(pt3, ct3);
            ps = cs; pt = ct; pt2 = ct2; pt3 = ct3;
        }
    }
    __syncthreads();

    // ---- Compute: thread -> 1 row (ty), col pairs {c0,c0+1} & {+64}, 8 j ----
    const int lx = tid & 31;
    const int ty = tid >> 5;                      // output row (0..7)
    const int c0 = lx * 2;

    ull acc[8][2];                                // [j][g]
    #pragma unroll
    for (int j = 0; j < 8; j++) {
        ull b = biasd[j];
        acc[j][0] = b; acc[j][1] = b;
    }

    #pragma unroll
    for (int f = 0; f < 4; f++) {
        #pragma unroll
        for (int dy = 0; dy < 3; dy++) {
            ull pr[2][3];                         // [g][dx]
            #pragma unroll
            for (int g = 0; g < 2; g++) {
                const float2* p = &Pm[((f * FROWS) + (ty + dy)) * PSTRIDE + c0 + g * 64];
                ulonglong2 v = *(const ulonglong2*)p;   // P[c0], P[c0+1]
                pr[g][0] = v.x;
                pr[g][1] = v.y;
                pr[g][2] = *(const ull*)(p + 2);        // P[c0+2]
            }
            #pragma unroll
            for (int dx = 0; dx < 3; dx++) {
                const ulonglong2* wp = (const ulonglong2*)&wsm[((dy * 3 + dx) * 4 + f) * 8];
                ulonglong2 w01 = wp[0], w23 = wp[1], w45 = wp[2], w67 = wp[3];
                #pragma unroll
                for (int g = 0; g < 2; g++) {
                    ull fv = pr[g][dx];
                    fma2(acc[0][g], fv, w01.x);
                    fma2(acc[1][g], fv, w01.y);
                    fma2(acc[2][g], fv, w23.x);
                    fma2(acc[3][g], fv, w23.y);
                    fma2(acc[4][g], fv, w45.x);
                    fma2(acc[5][g], fv, w45.y);
                    fma2(acc[6][g], fv, w67.x);
                    fma2(acc[7][g], fv, w67.y);
                }
            }
        }
    }

    // ---- stores: STG.64, coalesced per warp ----
    float* ob = out + ((size_t)(bc * NCONV) * H + (r0 + ty)) * W + c0;
    #pragma unroll
    for (int j = 0; j < 8; j++) {
        #pragma unroll
        for (int g = 0; g < 2; g++) {
            *(ull*)(ob + (size_t)j * (H * W) + g * 64) = acc[j][g];
        }
    }
}

extern "C" void kernel_launch(void* const* d_in, const int* in_sizes, int n_in,
                              void* d_out, int out_size) {
    const float* x     = (const float*)d_in[0];
    const float* cheby = (const float*)d_in[1];   // (8, 9, 4)
    const float* bw    = (const float*)d_in[2];   // (8, 9)
    const float* ss    = (const float*)d_in[3];   // (8, 9)
    float* out = (float*)d_out;

    cudaFuncSetAttribute(kan_conv_kernel,
                         cudaFuncAttributeMaxDynamicSharedMemorySize, SMEM_BYTES);

    const int planes = 16 * 16;                   // B * C
    dim3 grid(planes * (H / TILE_ROWS));          // 4096 blocks
    kan_conv_kernel<<<grid, NTHREADS, SMEM_BYTES>>>(x, cheby, bw, ss, out);
}

// round 4
// speedup vs baseline: 1.2430x; 1.0528x over previous
#include <cuda_runtime.h>

#define H 128
#define W 128
#define NCONV 8
#define TILE_ROWS 8
#define FROWS 10          // TILE_ROWS + 2 halo
#define PSTRIDE 132       // entries per row (129 used, padded)
#define NTHREADS 256

// dynamic smem layout (bytes)
#define OFF_P    0                                   // float2 P[4][10][132] = 42240
#define OFF_X    42240                               // float  x[10][132]    = 5280
#define OFF_W    47520                               // u64    w[288]        = 2304
#define OFF_B    49824                               // u64    bias[8]       = 64
#define SMEM_BYTES 49888

typedef unsigned long long ull;

__device__ __forceinline__ ull pk2(float lo, float hi) {
    ull r; asm("mov.b64 %0, {%1, %2};" : "=l"(r) : "f"(lo), "f"(hi)); return r;
}
__device__ __forceinline__ void fma2(ull &d, ull a, ull b) {
    asm("fma.rn.f32x2 %0, %1, %2, %0;" : "+l"(d) : "l"(a), "l"(b));
}

__device__ __forceinline__ void feats(float xv, float &s, float &t, float &t2, float &t3) {
    float e  = __expf(-xv);
    float d1 = __fdividef(1.f, 1.f + e);
    s = xv * d1;                                  // silu
    float e2 = e * e;                             // e^{-2x}
    float d2 = __fdividef(2.f, 1.f + e2);
    t  = d2 - 1.f;                                // tanh
    t2 = fmaf(t + t, t, -1.f);                    // T2
    t3 = fmaf(t + t, t2, -t);                     // T3
}

__global__ void __launch_bounds__(NTHREADS, 4)
kan_conv_kernel(const float* __restrict__ x,
                const float* __restrict__ cheby,
                const float* __restrict__ bw,
                const float* __restrict__ ss,
                float* __restrict__ out)
{
    extern __shared__ char smem_raw[];
    float2* Pm    = (float2*)(smem_raw + OFF_P);  // [f][row][k]: (feat[k-1], feat[k])
    float*  xsm   = (float*) (smem_raw + OFF_X);  // [row][i], i = col+1
    ull*    wsm   = (ull*)   (smem_raw + OFF_W);  // [(tap*4+f)*8 + j] dup pairs
    ull*    biasd = (ull*)   (smem_raw + OFF_B);

    const int tid = threadIdx.x;
    const int blk = blockIdx.x;
    const int bc  = blk >> 4;                     // plane b*C + c (0..255)
    const int r0  = (blk & 15) * TILE_ROWS;       // tile top row

    // ---- Phase A1: weights -> smem (duplicated f32x2 pairs) ----
    for (int idx = tid; idx < 9 * 4 * 8; idx += NTHREADS) {
        int j   = idx & 7;
        int fi  = idx >> 3;
        int tap = fi >> 2;
        int f   = fi & 3;
        float wv;
        if (f == 0) wv = bw[j * 9 + tap];
        else        wv = cheby[(j * 9 + tap) * 4 + f] * ss[j * 9 + tap];
        wsm[idx] = pk2(wv, wv);
    }
    if (tid < NCONV) {
        float s = 0.f;
        #pragma unroll
        for (int i = 0; i < 9; i++) s += cheby[(tid * 9 + i) * 4] * ss[tid * 9 + i];
        biasd[tid] = pk2(s, s);
    }

    // ---- Phase A2: x tile (zero halo) -> scalar smem, coalesced ----
    const float* xp = x + (size_t)bc * (H * W);
    for (int idx = tid; idx < FROWS * 130; idx += NTHREADS) {
        int lr = idx / 130;
        int c  = idx - lr * 130 - 1;              // col in [-1, 128]
        int gr = r0 - 1 + lr;
        float v = 0.f;
        if ((unsigned)gr < H && (unsigned)c < W) v = xp[gr * W + c];
        xsm[lr * PSTRIDE + (c + 1)] = v;
    }
    __syncthreads();

    // ---- Phase B: features -> pre-paired smem (220 threads, chunk=6) ----
    if (tid < FROWS * 22) {
        int row = tid / 22;
        int q   = tid - row * 22;
        int k0  = q * 6;
        const float* xr = &xsm[row * PSTRIDE];
        float ps, pt, pt2, pt3;
        feats(xr[k0], ps, pt, pt2, pt3);          // feat(col k0-1)
        int kend = k0 + 6; if (kend > 129) kend = 129;
        float2* P0 = &Pm[(0 * FROWS + row) * PSTRIDE];
        float2* P1 = &Pm[(1 * FROWS + row) * PSTRIDE];
        float2* P2 = &Pm[(2 * FROWS + row) * PSTRIDE];
        float2* P3 = &Pm[(3 * FROWS + row) * PSTRIDE];
        for (int k = k0; k < kend; k++) {
            float cs, ct, ct2, ct3;
            feats(xr[k + 1], cs, ct, ct2, ct3);   // feat(col k)
            P0[k] = make_float2(ps,  cs);
            P1[k] = make_float2(pt,  ct);
            P2[k] = make_float2(pt2, ct2);
            P3[k] = make_float2(pt3, ct3);
            ps = cs; pt = ct; pt2 = ct2; pt3 = ct3;
        }
    }
    __syncthreads();

    // ---- Compute: thread -> 1 row (ty), col pairs {c0,c0+1} & {+64}, 8 j ----
    const int lx = tid & 31;
    const int ty = tid >> 5;                      // output row (0..7)
    const int c0 = lx * 2;

    // single base pointers; all loop offsets become compile-time immediates
    const float2* Pbase = &Pm[(size_t)ty * PSTRIDE + c0];

    ull acc[8][2];                                // [j][g]
    #pragma unroll
    for (int j = 0; j < 8; j++) {
        ull b = biasd[j];
        acc[j][0] = b; acc[j][1] = b;
    }

    #pragma unroll
    for (int f = 0; f < 4; f++) {
        #pragma unroll
        for (int dy = 0; dy < 3; dy++) {
            ull pr[2][3];                         // [g][dx]
            #pragma unroll
            for (int g = 0; g < 2; g++) {
                const float2* p = Pbase + (f * FROWS + dy) * PSTRIDE + g * 64;
                ulonglong2 v = *(const ulonglong2*)p;   // P[c0], P[c0+1]
                pr[g][0] = v.x;
                pr[g][1] = v.y;
                pr[g][2] = *(const ull*)(p + 2);        // P[c0+2]
            }
            #pragma unroll
            for (int dx = 0; dx < 3; dx++) {
                const ulonglong2* wp = (const ulonglong2*)&wsm[((dy * 3 + dx) * 4 + f) * 8];
                {   // j 0..3 : only 8 weight regs live
                    ulonglong2 w01 = wp[0], w23 = wp[1];
                    #pragma unroll
                    for (int g = 0; g < 2; g++) {
                        ull fv = pr[g][dx];
                        fma2(acc[0][g], fv, w01.x);
                        fma2(acc[1][g], fv, w01.y);
                        fma2(acc[2][g], fv, w23.x);
                        fma2(acc[3][g], fv, w23.y);
                    }
                }
                {   // j 4..7
                    ulonglong2 w45 = wp[2], w67 = wp[3];
                    #pragma unroll
                    for (int g = 0; g < 2; g++) {
                        ull fv = pr[g][dx];
                        fma2(acc[4][g], fv, w45.x);
                        fma2(acc[5][g], fv, w45.y);
                        fma2(acc[6][g], fv, w67.x);
                        fma2(acc[7][g], fv, w67.y);
                    }
                }
            }
        }
    }

    // ---- stores: STG.64, coalesced per warp (addresses recomputed here) ----
    float* ob = out + ((size_t)(bc * NCONV) * H + (r0 + ty)) * W + c0;
    #pragma unroll
    for (int j = 0; j < 8; j++) {
        #pragma unroll
        for (int g = 0; g < 2; g++) {
            *(ull*)(ob + (size_t)j * (H * W) + g * 64) = acc[j][g];
        }
    }
}

extern "C" void kernel_launch(void* const* d_in, const int* in_sizes, int n_in,
                              void* d_out, int out_size) {
    const float* x     = (const float*)d_in[0];
    const float* cheby = (const float*)d_in[1];   // (8, 9, 4)
    const float* bw    = (const float*)d_in[2];   // (8, 9)
    const float* ss    = (const float*)d_in[3];   // (8, 9)
    float* out = (float*)d_out;

    cudaFuncSetAttribute(kan_conv_kernel,
                         cudaFuncAttributeMaxDynamicSharedMemorySize, SMEM_BYTES);

    const int planes = 16 * 16;                   // B * C
    dim3 grid(planes * (H / TILE_ROWS));          // 4096 blocks
    kan_conv_kernel<<<grid, NTHREADS, SMEM_BYTES>>>(x, cheby, bw, ss, out);
}

// round 5
// speedup vs baseline: 1.2767x; 1.0271x over previous
#include <cuda_runtime.h>

#define H 128
#define W 128
#define NCONV 8
#define TILE_ROWS 8
#define FROWS 10          // TILE_ROWS + 2 halo
#define PSTRIDE 132       // pair entries per row (129 used, padded)
#define NTHREADS 256

// dynamic smem layout (bytes)
#define OFF_P    0                                   // float2 P[4][10][132] = 42240
#define OFF_W    42240                               // u64    w[288]        = 2304
#define OFF_B    44544                               // u64    bias[8]       = 64
#define SMEM_BYTES 44608

typedef unsigned long long ull;

__device__ __forceinline__ ull pk2(float lo, float hi) {
    ull r; asm("mov.b64 %0, {%1, %2};" : "=l"(r) : "f"(lo), "f"(hi)); return r;
}
__device__ __forceinline__ void fma2(ull &d, ull a, ull b) {
    asm("fma.rn.f32x2 %0, %1, %2, %0;" : "+l"(d) : "l"(a), "l"(b));
}
__device__ __forceinline__ float tanh_ap(float x) {
    float r; asm("tanh.approx.f32 %0, %1;" : "=f"(r) : "f"(x)); return r;
}

// features of one input value: 2 MUFU + a few fma
__device__ __forceinline__ void feats(float xv, float &s, float &t, float &t2, float &t3) {
    t = tanh_ap(xv);                               // tanh
    float th = tanh_ap(0.5f * xv);
    float sg = fmaf(0.5f, th, 0.5f);               // sigmoid(x)
    s  = xv * sg;                                  // silu
    t2 = fmaf(t + t, t, -1.f);                     // T2
    t3 = fmaf(t + t, t2, -t);                      // T3
}

__global__ void __launch_bounds__(NTHREADS, 4)
kan_conv_kernel(const float* __restrict__ x,
                const float* __restrict__ cheby,
                const float* __restrict__ bw,
                const float* __restrict__ ss,
                float* __restrict__ out)
{
    extern __shared__ char smem_raw[];
    float2* Pm    = (float2*)(smem_raw + OFF_P);  // [f][row][k]: (F(k), F(k+1)), F(i)=feat(col i-1)
    ull*    wsm   = (ull*)   (smem_raw + OFF_W);  // [(tap*4+f)*8 + j] dup pairs
    ull*    biasd = (ull*)   (smem_raw + OFF_B);

    const int tid  = threadIdx.x;
    const int wid  = tid >> 5;
    const int lane = tid & 31;
    const int blk  = blockIdx.x;
    const int bc   = blk >> 4;                    // plane b*C + c (0..255)
    const int r0   = (blk & 15) * TILE_ROWS;      // tile top row

    // ---- Phase A: weights -> smem (duplicated f32x2 pairs) ----
    for (int idx = tid; idx < 9 * 4 * 8; idx += NTHREADS) {
        int j   = idx & 7;
        int fi  = idx >> 3;
        int tap = fi >> 2;
        int f   = fi & 3;
        float wv;
        if (f == 0) wv = bw[j * 9 + tap];
        else        wv = cheby[(j * 9 + tap) * 4 + f] * ss[j * 9 + tap];
        wsm[idx] = pk2(wv, wv);
    }
    if (tid < NCONV) {
        float sum = 0.f;
        #pragma unroll
        for (int i = 0; i < 9; i++) sum += cheby[(tid * 9 + i) * 4] * ss[tid * 9 + i];
        biasd[tid] = pk2(sum, sum);
    }

    // ---- Phase B: features gmem -> pre-paired smem, conflict-free, parallel ----
    // warp task = (row, 31-wide chunk c); lane evaluates F(i), i = 31c + lane;
    // lanes 1..31 store P[k]=(F(k),F(k+1)) at k = i-1 : 8B-contiguous, no conflicts.
    const float* xp = x + (size_t)bc * (H * W);
    for (int task = wid; task < FROWS * 5; task += NTHREADS / 32) {
        int row = task / 5;                        // 0..9
        int c   = task - row * 5;                  // 0..4
        int i   = c * 31 + lane;                   // feature index (col = i-1)
        int gr  = r0 - 1 + row;
        int col = i - 1;
        float xv = 0.f;
        if ((unsigned)gr < H && (unsigned)col < W) xv = xp[gr * W + col];
        float s, t, t2, t3;
        feats(xv, s, t, t2, t3);                   // x=0 padding -> (0,0,-1,0) ✓
        float ps  = __shfl_up_sync(0xffffffffu, s,  1);
        float pt  = __shfl_up_sync(0xffffffffu, t,  1);
        float pt2 = __shfl_up_sync(0xffffffffu, t2, 1);
        float pt3 = __shfl_up_sync(0xffffffffu, t3, 1);
        int k = i - 1;
        if (lane >= 1 && k <= 128) {
            Pm[(0 * FROWS + row) * PSTRIDE + k] = make_float2(ps,  s);
            Pm[(1 * FROWS + row) * PSTRIDE + k] = make_float2(pt,  t);
            Pm[(2 * FROWS + row) * PSTRIDE + k] = make_float2(pt2, t2);
            Pm[(3 * FROWS + row) * PSTRIDE + k] = make_float2(pt3, t3);
        }
    }
    __syncthreads();

    // ---- Compute: thread -> 1 row (ty), col pairs {c0,c0+1} & {+64}, 8 j ----
    const int ty = wid;                            // output row (0..7)
    const int c0 = lane * 2;

    const float2* Pbase = &Pm[(size_t)ty * PSTRIDE + c0];

    ull acc[8][2];                                 // [j][g]
    #pragma unroll
    for (int j = 0; j < 8; j++) {
        ull b = biasd[j];
        acc[j][0] = b; acc[j][1] = b;
    }

    #pragma unroll
    for (int f = 0; f < 4; f++) {
        #pragma unroll
        for (int dy = 0; dy < 3; dy++) {
            ull pr[2][3];                          // [g][dx]
            #pragma unroll
            for (int g = 0; g < 2; g++) {
                const float2* p = Pbase + (f * FROWS + dy) * PSTRIDE + g * 64;
                ulonglong2 v = *(const ulonglong2*)p;    // P[c0], P[c0+1]
                pr[g][0] = v.x;
                pr[g][1] = v.y;
                pr[g][2] = *(const ull*)(p + 2);         // P[c0+2]
            }
            #pragma unroll
            for (int dx = 0; dx < 3; dx++) {
                const ulonglong2* wp = (const ulonglong2*)&wsm[((dy * 3 + dx) * 4 + f) * 8];
                {   // j 0..3
                    ulonglong2 w01 = wp[0], w23 = wp[1];
                    #pragma unroll
                    for (int g = 0; g < 2; g++) {
                        ull fv = pr[g][dx];
                        fma2(acc[0][g], fv, w01.x);
                        fma2(acc[1][g], fv, w01.y);
                        fma2(acc[2][g], fv, w23.x);
                        fma2(acc[3][g], fv, w23.y);
                    }
                }
                {   // j 4..7
                    ulonglong2 w45 = wp[2], w67 = wp[3];
                    #pragma unroll
                    for (int g = 0; g < 2; g++) {
                        ull fv = pr[g][dx];
                        fma2(acc[4][g], fv, w45.x);
                        fma2(acc[5][g], fv, w45.y);
                        fma2(acc[6][g], fv, w67.x);
                        fma2(acc[7][g], fv, w67.y);
                    }
                }
            }
        }
    }

    // ---- stores: STG.64, coalesced per warp ----
    float* ob = out + ((size_t)(bc * NCONV) * H + (r0 + ty)) * W + c0;
    #pragma unroll
    for (int j = 0; j < 8; j++) {
        #pragma unroll
        for (int g = 0; g < 2; g++) {
            *(ull*)(ob + (size_t)j * (H * W) + g * 64) = acc[j][g];
        }
    }
}

extern "C" void kernel_launch(void* const* d_in, const int* in_sizes, int n_in,
                              void* d_out, int out_size) {
    const float* x     = (const float*)d_in[0];
    const float* cheby = (const float*)d_in[1];   // (8, 9, 4)
    const float* bw    = (const float*)d_in[2];   // (8, 9)
    const float* ss    = (const float*)d_in[3];   // (8, 9)
    float* out = (float*)d_out;

    cudaFuncSetAttribute(kan_conv_kernel,
                         cudaFuncAttributeMaxDynamicSharedMemorySize, SMEM_BYTES);

    const int planes = 16 * 16;                   // B * C
    dim3 grid(planes * (H / TILE_ROWS));          // 4096 blocks
    kan_conv_kernel<<<grid, NTHREADS, SMEM_BYTES>>>(x, cheby, bw, ss, out);
}